// round 1
// baseline (speedup 1.0000x reference)
#include <cuda_runtime.h>
#include <cstdint>

// Problem constants
#define D 256
#define NH 8
#define HD 32
#define LEV 3
#define NP 4
#define DFF 1024
#define BB 8
#define LQ 3600
#define NTOK (LQ * BB)          // 28800 tgt tokens (token t = lq*8 + b)
#define LIN 4725
#define NVTOK (BB * LIN)        // 37800 src tokens

// ---------------- scratch (device globals; no allocation in kernel_launch) ---
__device__ float g_qkv[NTOK * 3 * D];       // [t][0:768] q|k|v
__device__ float g_ctx[NTOK * D];
__device__ float g_x1[NTOK * D];            // after LN2
__device__ float g_x2[NTOK * D];            // after LN1
__device__ float g_val[NVTOK * D];          // value proj, [b][i][d]
__device__ float g_off[NTOK * 288];         // 192 offsets + 96 attn logits
__device__ float g_ms[NTOK * D];            // deform-sampled output
__device__ float g_tmp[NTOK * D];           // generic 256-wide temp
__device__ float g_h[NTOK * DFF];           // ffn hidden
__device__ float g_bias768[768];
__device__ float g_bias288[288];

// ---------------- bias folding: b' = b + W @ query_pos ----------------------
__global__ void bias_adjust_kernel(const float* __restrict__ ipw, const float* __restrict__ ipb,
                                   const float* __restrict__ sow, const float* __restrict__ sob,
                                   const float* __restrict__ aww, const float* __restrict__ awb,
                                   const float* __restrict__ qp)
{
    int w = blockIdx.x * (blockDim.x >> 5) + (threadIdx.x >> 5);
    int lane = threadIdx.x & 31;
    if (w < 768) {
        float s = 0.f;
        if (w < 512) {  // q,k rows get query_pos folded in; v rows do not
            const float* row = ipw + (size_t)w * D;
            #pragma unroll
            for (int i = 0; i < 8; i++) s += row[lane + i * 32] * qp[lane + i * 32];
            #pragma unroll
            for (int o = 16; o > 0; o >>= 1) s += __shfl_xor_sync(~0u, s, o);
        }
        if (lane == 0) g_bias768[w] = ipb[w] + s;
    } else if (w < 768 + 288) {
        int j = w - 768;
        const float* row; float bb;
        if (j < 192) { row = sow + (size_t)j * D; bb = sob[j]; }
        else         { row = aww + (size_t)(j - 192) * D; bb = awb[j - 192]; }
        float s = 0.f;
        #pragma unroll
        for (int i = 0; i < 8; i++) s += row[lane + i * 32] * qp[lane + i * 32];
        #pragma unroll
        for (int o = 16; o > 0; o >>= 1) s += __shfl_xor_sync(~0u, s, o);
        if (lane == 0) g_bias288[j] = bb + s;
    }
}

// ---------------- generic fp32 GEMM: C[m, col_off+n] = A[m,:K] . W[n,:K] + bias[n]
// A: MxK row-major, W: NxK row-major (so C = A @ W^T). 128x128x16 tile, 8x8/thr.
#define BM 128
#define BN 128
#define BK 16
__global__ __launch_bounds__(256, 2)
void gemm_kernel(const float* __restrict__ A, const float* __restrict__ W,
                 const float* __restrict__ bias, float* __restrict__ C,
                 int M, int N, int K, int ldc, int col_off, int relu)
{
    __shared__ float As[BK][BM];
    __shared__ float Bs[BK][BN];
    int tid = threadIdx.x;
    int m0 = blockIdx.y * BM;
    int n0 = blockIdx.x * BN;
    int tx = tid & 15, ty = tid >> 4;
    int lr = tid >> 2;            // 0..63
    int lc = (tid & 3) * 4;       // 0,4,8,12
    float acc[8][8] = {};
    for (int k0 = 0; k0 < K; k0 += BK) {
        #pragma unroll
        for (int p = 0; p < 2; p++) {
            int r = lr + p * 64;
            int m = m0 + r;
            float4 va = (m < M) ? *(const float4*)(A + (size_t)m * K + k0 + lc)
                                : make_float4(0.f, 0.f, 0.f, 0.f);
            As[lc + 0][r] = va.x; As[lc + 1][r] = va.y;
            As[lc + 2][r] = va.z; As[lc + 3][r] = va.w;
            int n = n0 + r;
            float4 vb = (n < N) ? *(const float4*)(W + (size_t)n * K + k0 + lc)
                                : make_float4(0.f, 0.f, 0.f, 0.f);
            Bs[lc + 0][r] = vb.x; Bs[lc + 1][r] = vb.y;
            Bs[lc + 2][r] = vb.z; Bs[lc + 3][r] = vb.w;
        }
        __syncthreads();
        #pragma unroll
        for (int k = 0; k < BK; k++) {
            float a[8], b[8];
            *(float4*)(a)     = *(const float4*)&As[k][ty * 8];
            *(float4*)(a + 4) = *(const float4*)&As[k][ty * 8 + 4];
            *(float4*)(b)     = *(const float4*)&Bs[k][tx * 8];
            *(float4*)(b + 4) = *(const float4*)&Bs[k][tx * 8 + 4];
            #pragma unroll
            for (int i = 0; i < 8; i++)
                #pragma unroll
                for (int j = 0; j < 8; j++)
                    acc[i][j] += a[i] * b[j];
        }
        __syncthreads();
    }
    #pragma unroll
    for (int i = 0; i < 8; i++) {
        int m = m0 + ty * 8 + i;
        if (m >= M) continue;
        #pragma unroll
        for (int j = 0; j < 8; j++) {
            int n = n0 + tx * 8 + j;
            if (n >= N) continue;
            float v = acc[i][j] + bias[n];
            if (relu) v = fmaxf(v, 0.f);
            C[(size_t)m * ldc + col_off + n] = v;
        }
    }
}

// ---------------- self-attention over the 8-element batch axis per query ----
__global__ void self_attn_kernel(const float* __restrict__ qkv, float* __restrict__ ctx)
{
    int lq = blockIdx.x;
    __shared__ float qs[8][260], ks[8][260], vs[8][260];
    __shared__ float att[8][8][8]; // [head][b1][b2]
    int tid = threadIdx.x;
    for (int idx = tid; idx < 8 * 256; idx += 256) {
        int b = idx >> 8;
        int d = idx & 255;
        const float* row = qkv + (size_t)(lq * 8 + b) * 768;
        qs[b][d] = row[d];
        ks[b][d] = row[256 + d];
        vs[b][d] = row[512 + d];
    }
    __syncthreads();
    int h = tid >> 5;
    int lane = tid & 31;
    {
        int p0 = lane, p1 = lane + 32;
        int b1a = p0 >> 3, b2a = p0 & 7;
        int b1b = p1 >> 3, b2b = p1 & 7;
        const float* qa = &qs[b1a][h * 32]; const float* ka = &ks[b2a][h * 32];
        const float* qb = &qs[b1b][h * 32]; const float* kb = &ks[b2b][h * 32];
        float l0 = 0.f, l1 = 0.f;
        #pragma unroll
        for (int j = 0; j < 32; j++) { l0 += qa[j] * ka[j]; l1 += qb[j] * kb[j]; }
        const float scale = 0.17677669529663687f; // 1/sqrt(32)
        att[h][b1a][b2a] = l0 * scale;
        att[h][b1b][b2b] = l1 * scale;
    }
    __syncwarp();
    if (lane < 8) {
        float* r = att[h][lane];
        float mx = r[0];
        #pragma unroll
        for (int j = 1; j < 8; j++) mx = fmaxf(mx, r[j]);
        float e[8]; float s = 0.f;
        #pragma unroll
        for (int j = 0; j < 8; j++) { e[j] = __expf(r[j] - mx); s += e[j]; }
        float inv = 1.f / s;
        #pragma unroll
        for (int j = 0; j < 8; j++) r[j] = e[j] * inv;
    }
    __syncwarp();
    #pragma unroll
    for (int b1 = 0; b1 < 8; b1++) {
        float acc = 0.f;
        #pragma unroll
        for (int b2 = 0; b2 < 8; b2++) acc += att[h][b1][b2] * vs[b2][h * 32 + lane];
        ctx[(size_t)(lq * 8 + b1) * 256 + h * 32 + lane] = acc;
    }
}

// ---------------- fused residual + LayerNorm (warp per token) ---------------
__global__ void ln_residual_kernel(const float* __restrict__ x, const float* __restrict__ y,
                                   const float* __restrict__ g, const float* __restrict__ b,
                                   float* __restrict__ out, int ntok)
{
    int t = blockIdx.x * (blockDim.x >> 5) + (threadIdx.x >> 5);
    if (t >= ntok) return;
    int lane = threadIdx.x & 31;
    const float* xr = x + (size_t)t * 256;
    const float* yr = y + (size_t)t * 256;
    float v[8]; float s = 0.f;
    #pragma unroll
    for (int i = 0; i < 8; i++) { v[i] = xr[lane + i * 32] + yr[lane + i * 32]; s += v[i]; }
    #pragma unroll
    for (int o = 16; o > 0; o >>= 1) s += __shfl_xor_sync(~0u, s, o);
    float mean = s * (1.f / 256.f);
    float var = 0.f;
    #pragma unroll
    for (int i = 0; i < 8; i++) { float d = v[i] - mean; var += d * d; }
    #pragma unroll
    for (int o = 16; o > 0; o >>= 1) var += __shfl_xor_sync(~0u, var, o);
    float inv = rsqrtf(var * (1.f / 256.f) + 1e-5f);
    #pragma unroll
    for (int i = 0; i < 8; i++) {
        int d = lane + i * 32;
        out[(size_t)t * 256 + d] = (v[i] - mean) * inv * g[d] + b[d];
    }
}

// ---------------- MS-deformable bilinear sampling (warp per (t, head)) ------
__global__ void msdeform_sample_kernel(const float* __restrict__ off,
                                       const float* __restrict__ val,
                                       float* __restrict__ out)
{
    int t = blockIdx.x;
    int lq = t >> 3, b = t & 7;
    int h = threadIdx.x >> 5;
    int lane = threadIdx.x & 31;
    int r = lq / 60, c = lq % 60;
    float refx = (c + 0.5f) * (1.f / 60.f);
    float refy = (r + 0.5f) * (1.f / 60.f);
    const float* ob = off + (size_t)t * 288;

    float wgt[12];
    {
        float mx = -1e30f;
        #pragma unroll
        for (int j = 0; j < 12; j++) { wgt[j] = ob[192 + h * 12 + j]; mx = fmaxf(mx, wgt[j]); }
        float s = 0.f;
        #pragma unroll
        for (int j = 0; j < 12; j++) { wgt[j] = __expf(wgt[j] - mx); s += wgt[j]; }
        float inv = 1.f / s;
        #pragma unroll
        for (int j = 0; j < 12; j++) wgt[j] *= inv;
    }

    const int HL[3] = {60, 30, 15};
    const int SL[3] = {0, 3600, 4500};
    float acc = 0.f;
    const float* vbase = val + (size_t)b * LIN * 256 + h * 32 + lane;
    #pragma unroll
    for (int l = 0; l < 3; l++) {
        int Wl = HL[l], Hl = HL[l];
        const float* vb = vbase + (size_t)SL[l] * 256;
        #pragma unroll
        for (int p = 0; p < 4; p++) {
            float ox = ob[((h * 3 + l) * 4 + p) * 2 + 0];
            float oy = ob[((h * 3 + l) * 4 + p) * 2 + 1];
            float x = refx * (float)Wl + ox - 0.5f;   // (refx + ox/Wl)*Wl - 0.5
            float y = refy * (float)Hl + oy - 0.5f;
            float x0f = floorf(x), y0f = floorf(y);
            float fx = x - x0f, fy = y - y0f;
            int x0 = (int)x0f, y0 = (int)y0f;
            float aw = wgt[l * 4 + p];
            float res = 0.f;
            #pragma unroll
            for (int cy = 0; cy < 2; cy++) {
                int yi = y0 + cy;
                if (yi < 0 || yi >= Hl) continue;
                float wy = cy ? fy : (1.f - fy);
                #pragma unroll
                for (int cx = 0; cx < 2; cx++) {
                    int xi = x0 + cx;
                    if (xi < 0 || xi >= Wl) continue;
                    float wx = cx ? fx : (1.f - fx);
                    res += wy * wx * vb[(size_t)(yi * Wl + xi) * 256];
                }
            }
            acc += aw * res;
        }
    }
    out[(size_t)t * 256 + h * 32 + lane] = acc;
}

// ---------------- host launch ------------------------------------------------
static void gemm_launch(const float* A, const float* W, const float* bias, float* C,
                        int M, int N, int K, int ldc, int col_off, int relu)
{
    dim3 grid((N + BN - 1) / BN, (M + BM - 1) / BM);
    gemm_kernel<<<grid, 256>>>(A, W, bias, C, M, N, K, ldc, col_off, relu);
}

extern "C" void kernel_launch(void* const* d_in, const int* in_sizes, int n_in,
                              void* d_out, int out_size)
{
    const float* tgt = (const float*)d_in[0];
    const float* qp  = (const float*)d_in[1];
    const float* src = (const float*)d_in[2];
    // d_in[3], d_in[4]: spatial shapes / level starts (compile-time constants here)
    const float* ipw = (const float*)d_in[5];
    const float* ipb = (const float*)d_in[6];
    const float* opw = (const float*)d_in[7];
    const float* opb = (const float*)d_in[8];
    const float* sow = (const float*)d_in[9];
    const float* sob = (const float*)d_in[10];
    const float* aww = (const float*)d_in[11];
    const float* awb = (const float*)d_in[12];
    const float* vpw = (const float*)d_in[13];
    const float* vpb = (const float*)d_in[14];
    const float* cow = (const float*)d_in[15];
    const float* cob = (const float*)d_in[16];
    const float* ln1g = (const float*)d_in[17];
    const float* ln1b = (const float*)d_in[18];
    const float* ln2g = (const float*)d_in[19];
    const float* ln2b = (const float*)d_in[20];
    const float* ln3g = (const float*)d_in[21];
    const float* ln3b = (const float*)d_in[22];
    const float* fw1 = (const float*)d_in[23];
    const float* fb1 = (const float*)d_in[24];
    const float* fw2 = (const float*)d_in[25];
    const float* fb2 = (const float*)d_in[26];
    float* out = (float*)d_out;

    float *p_qkv, *p_ctx, *p_x1, *p_x2, *p_val, *p_off, *p_ms, *p_tmp, *p_h, *p_b768, *p_b288;
    cudaGetSymbolAddress((void**)&p_qkv, g_qkv);
    cudaGetSymbolAddress((void**)&p_ctx, g_ctx);
    cudaGetSymbolAddress((void**)&p_x1,  g_x1);
    cudaGetSymbolAddress((void**)&p_x2,  g_x2);
    cudaGetSymbolAddress((void**)&p_val, g_val);
    cudaGetSymbolAddress((void**)&p_off, g_off);
    cudaGetSymbolAddress((void**)&p_ms,  g_ms);
    cudaGetSymbolAddress((void**)&p_tmp, g_tmp);
    cudaGetSymbolAddress((void**)&p_h,   g_h);
    cudaGetSymbolAddress((void**)&p_b768, g_bias768);
    cudaGetSymbolAddress((void**)&p_b288, g_bias288);

    // 1. fold query_pos into projection biases
    bias_adjust_kernel<<<132, 256>>>(ipw, ipb, sow, sob, aww, awb, qp);

    // 2. QKV projection: (tgt @ in_proj_w^T) + folded bias  -> [t][768]
    gemm_launch(tgt, ipw, p_b768, p_qkv, NTOK, 768, 256, 768, 0, 0);

    // 3. batch-axis self-attention (8x8 per (lq, head))
    self_attn_kernel<<<LQ, 256>>>(p_qkv, p_ctx);

    // 4. out projection
    gemm_launch(p_ctx, opw, opb, p_tmp, NTOK, 256, 256, 256, 0, 0);

    // 5. t = LN2(tgt + tgt2)
    ln_residual_kernel<<<NTOK / 8, 256>>>(tgt, p_tmp, ln2g, ln2b, p_x1, NTOK);

    // 6. value projection of src
    gemm_launch(src, vpw, vpb, p_val, NVTOK, 256, 256, 256, 0, 0);

    // 7+8. sampling offsets (192) and attention-weight logits (96), qp folded in bias
    gemm_launch(p_x1, sow, p_b288,       p_off, NTOK, 192, 256, 288, 0,   0);
    gemm_launch(p_x1, aww, p_b288 + 192, p_off, NTOK,  96, 256, 288, 192, 0);

    // 9. deformable bilinear sampling + weighted aggregation
    msdeform_sample_kernel<<<NTOK, 256>>>(p_off, p_val, p_ms);

    // 10. cross-attn output projection
    gemm_launch(p_ms, cow, cob, p_tmp, NTOK, 256, 256, 256, 0, 0);

    // 11. tq = LN1(t + tgt2)
    ln_residual_kernel<<<NTOK / 8, 256>>>(p_x1, p_tmp, ln1g, ln1b, p_x2, NTOK);

    // 12. FFN up + relu
    gemm_launch(p_x2, fw1, fb1, p_h, NTOK, DFF, 256, DFF, 0, 1);

    // 13. FFN down
    gemm_launch(p_h, fw2, fb2, p_tmp, NTOK, 256, DFF, 256, 0, 0);

    // 14. out = LN3(tq + ff) -> d_out (token-major == (LQ, B, D))
    ln_residual_kernel<<<NTOK / 8, 256>>>(p_x2, p_tmp, ln3g, ln3b, out, NTOK);
}

// round 2
// speedup vs baseline: 2.1817x; 2.1817x over previous
#include <cuda_runtime.h>
#include <cstdint>

// Problem constants
#define D 256
#define NH 8
#define HD 32
#define DFF 1024
#define BB 8
#define LQ 3600
#define NTOK (LQ * BB)          // 28800 tgt tokens (token t = lq*8 + b)
#define LIN 4725
#define NVTOK (BB * LIN)        // 37800 src tokens

// ---------------- scratch (device globals; no allocation at launch) ---------
__device__ float g_qkv[NTOK * 3 * D];
__device__ float g_ctx[NTOK * D];
__device__ float g_x1[NTOK * D];
__device__ float g_x2[NTOK * D];
__device__ float g_val[NVTOK * D];
__device__ float g_off[NTOK * 288];
__device__ float g_ms[NTOK * D];
__device__ float g_tmp[NTOK * D];
__device__ float g_h[NTOK * DFF];
__device__ float g_bias768[768];
__device__ float g_bias288[288];
// tf32-rounded copies
__device__ float g_tgt_r[NTOK * D];
__device__ float g_src_r[NVTOK * D];
__device__ float g_ipw[768 * 256];
__device__ float g_opw[256 * 256];
__device__ float g_w288[288 * 256];     // [0:192) samp_off rows, [192:288) attn_w rows
__device__ float g_vpw[256 * 256];
__device__ float g_cow[256 * 256];
__device__ float g_fw1[1024 * 256];
__device__ float g_fw2[256 * 1024];

__device__ __forceinline__ float to_tf32(float x) {
    uint32_t u;
    asm("cvt.rna.tf32.f32 %0, %1;" : "=r"(u) : "f"(x));
    return __uint_as_float(u);
}

// ---------------- round-to-tf32 copy ----------------------------------------
__global__ void round_copy_kernel(const float* __restrict__ s, float* __restrict__ d, int n)
{
    int i = (blockIdx.x * 256 + threadIdx.x) * 4;
    if (i < n) {
        float4 v = *(const float4*)(s + i);
        v.x = to_tf32(v.x); v.y = to_tf32(v.y);
        v.z = to_tf32(v.z); v.w = to_tf32(v.w);
        *(float4*)(d + i) = v;
    }
}

// ---------------- bias folding: b' = b + W @ query_pos ----------------------
__global__ void bias_adjust_kernel(const float* __restrict__ ipw, const float* __restrict__ ipb,
                                   const float* __restrict__ sow, const float* __restrict__ sob,
                                   const float* __restrict__ aww, const float* __restrict__ awb,
                                   const float* __restrict__ qp)
{
    int w = blockIdx.x * (blockDim.x >> 5) + (threadIdx.x >> 5);
    int lane = threadIdx.x & 31;
    if (w < 768) {
        float s = 0.f;
        if (w < 512) {  // q,k rows get query_pos folded in; v rows do not
            const float* row = ipw + (size_t)w * D;
            #pragma unroll
            for (int i = 0; i < 8; i++) s += row[lane + i * 32] * qp[lane + i * 32];
            #pragma unroll
            for (int o = 16; o > 0; o >>= 1) s += __shfl_xor_sync(~0u, s, o);
        }
        if (lane == 0) g_bias768[w] = ipb[w] + s;
    } else if (w < 768 + 288) {
        int j = w - 768;
        const float* row; float bb;
        if (j < 192) { row = sow + (size_t)j * D; bb = sob[j]; }
        else         { row = aww + (size_t)(j - 192) * D; bb = awb[j - 192]; }
        float s = 0.f;
        #pragma unroll
        for (int i = 0; i < 8; i++) s += row[lane + i * 32] * qp[lane + i * 32];
        #pragma unroll
        for (int o = 16; o > 0; o >>= 1) s += __shfl_xor_sync(~0u, s, o);
        if (lane == 0) g_bias288[j] = bb + s;
    }
}

// ---------------- tf32 tensor-core GEMM: C = A @ W^T + bias -----------------
// A: MxK row-major (tf32-rounded). W: NxK row-major (tf32-rounded).
// 128x128 block tile, BK=32, 8 warps (2x4), warp tile 64x32, mma.m16n8k8.
#define BM 128
#define BN 128
#define SROW 36                           // padded smem row stride (floats)
#define STAGE_SZ (2 * BM * SROW)          // A-tile + B-tile, floats

__device__ __forceinline__ void gemm_load_tile(
    const float* __restrict__ A, const float* __restrict__ W,
    int M, int N, int K, int m0, int n0, int k0,
    float* __restrict__ stage_base, int tid)
{
    float* As = stage_base;
    float* Bs = stage_base + BM * SROW;
    #pragma unroll
    for (int i = 0; i < 4; i++) {
        int idx = tid + i * 256;
        int row = idx >> 3, ch = (idx & 7) * 4;
        int mr = m0 + row; if (mr >= M) mr = M - 1;
        const float* gsrc = A + (size_t)mr * K + k0 + ch;
        uint32_t sdst = (uint32_t)__cvta_generic_to_shared(As + row * SROW + ch);
        asm volatile("cp.async.cg.shared.global [%0], [%1], 16;\n" :: "r"(sdst), "l"(gsrc));
    }
    #pragma unroll
    for (int i = 0; i < 4; i++) {
        int idx = tid + i * 256;
        int row = idx >> 3, ch = (idx & 7) * 4;
        int nr = n0 + row; if (nr >= N) nr = N - 1;
        const float* gsrc = W + (size_t)nr * K + k0 + ch;
        uint32_t sdst = (uint32_t)__cvta_generic_to_shared(Bs + row * SROW + ch);
        asm volatile("cp.async.cg.shared.global [%0], [%1], 16;\n" :: "r"(sdst), "l"(gsrc));
    }
    asm volatile("cp.async.commit_group;\n");
}

__global__ __launch_bounds__(256)
void gemm_tf32_kernel(const float* __restrict__ A, const float* __restrict__ W,
                      const float* __restrict__ bias, float* __restrict__ C,
                      int M, int N, int K, int ldc, int relu, int rnd)
{
    extern __shared__ float smem[];
    int tid = threadIdx.x;
    int wid = tid >> 5, lane = tid & 31;
    int g = lane >> 2, t = lane & 3;
    int wm = wid >> 2, wn = wid & 3;       // 2 x 4 warp grid
    int m0 = blockIdx.y * BM, n0 = blockIdx.x * BN;

    float acc[4][4][4];
    #pragma unroll
    for (int i = 0; i < 4; i++)
        #pragma unroll
        for (int j = 0; j < 4; j++)
            #pragma unroll
            for (int c = 0; c < 4; c++) acc[i][j][c] = 0.f;

    int niter = K >> 5;
    gemm_load_tile(A, W, M, N, K, m0, n0, 0, smem, tid);

    for (int it = 0; it < niter; ++it) {
        if (it + 1 < niter) {
            gemm_load_tile(A, W, M, N, K, m0, n0, (it + 1) << 5,
                           smem + ((it + 1) & 1) * STAGE_SZ, tid);
            asm volatile("cp.async.wait_group 1;\n" ::: "memory");
        } else {
            asm volatile("cp.async.wait_group 0;\n" ::: "memory");
        }
        __syncthreads();

        const float* As = smem + (it & 1) * STAGE_SZ;
        const float* Bs = As + BM * SROW;
        #pragma unroll
        for (int ks = 0; ks < 4; ks++) {
            int kc = ks * 8;
            uint32_t a[4][4], b[4][2];
            #pragma unroll
            for (int mt = 0; mt < 4; mt++) {
                int r = wm * 64 + mt * 16 + g;
                const uint32_t* p  = (const uint32_t*)(As + r * SROW + kc + t);
                const uint32_t* p2 = (const uint32_t*)(As + (r + 8) * SROW + kc + t);
                a[mt][0] = p[0];  a[mt][2] = p[4];
                a[mt][1] = p2[0]; a[mt][3] = p2[4];
            }
            #pragma unroll
            for (int nt = 0; nt < 4; nt++) {
                int r = wn * 32 + nt * 8 + g;
                const uint32_t* p = (const uint32_t*)(Bs + r * SROW + kc + t);
                b[nt][0] = p[0]; b[nt][1] = p[4];
            }
            #pragma unroll
            for (int mt = 0; mt < 4; mt++)
                #pragma unroll
                for (int nt = 0; nt < 4; nt++) {
                    asm volatile(
                        "mma.sync.aligned.m16n8k8.row.col.f32.tf32.tf32.f32 "
                        "{%0,%1,%2,%3}, {%4,%5,%6,%7}, {%8,%9}, {%0,%1,%2,%3};\n"
                        : "+f"(acc[mt][nt][0]), "+f"(acc[mt][nt][1]),
                          "+f"(acc[mt][nt][2]), "+f"(acc[mt][nt][3])
                        : "r"(a[mt][0]), "r"(a[mt][1]), "r"(a[mt][2]), "r"(a[mt][3]),
                          "r"(b[nt][0]), "r"(b[nt][1]));
                }
        }
        __syncthreads();
    }

    // epilogue
    #pragma unroll
    for (int mt = 0; mt < 4; mt++) {
        int m = m0 + wm * 64 + mt * 16 + g;
        #pragma unroll
        for (int nt = 0; nt < 4; nt++) {
            int n = n0 + wn * 32 + nt * 8 + 2 * t;
            if (n >= N) continue;                   // N is always even; pair all-or-none
            float b0 = bias[n], b1 = bias[n + 1];
            float v0 = acc[mt][nt][0] + b0, v1 = acc[mt][nt][1] + b1;
            float v2 = acc[mt][nt][2] + b0, v3 = acc[mt][nt][3] + b1;
            if (relu) {
                v0 = fmaxf(v0, 0.f); v1 = fmaxf(v1, 0.f);
                v2 = fmaxf(v2, 0.f); v3 = fmaxf(v3, 0.f);
            }
            if (rnd) {
                v0 = to_tf32(v0); v1 = to_tf32(v1);
                v2 = to_tf32(v2); v3 = to_tf32(v3);
            }
            if (m < M)     *(float2*)(C + (size_t)m * ldc + n)       = make_float2(v0, v1);
            if (m + 8 < M) *(float2*)(C + (size_t)(m + 8) * ldc + n) = make_float2(v2, v3);
        }
    }
}

// ---------------- self-attention over the 8-element batch axis per query ----
__global__ void self_attn_kernel(const float* __restrict__ qkv, float* __restrict__ ctx)
{
    int lq = blockIdx.x;
    __shared__ float qs[8][260], ks[8][260], vs[8][260];
    __shared__ float att[8][8][8];
    int tid = threadIdx.x;
    for (int idx = tid; idx < 8 * 256; idx += 256) {
        int b = idx >> 8;
        int d = idx & 255;
        const float* row = qkv + (size_t)(lq * 8 + b) * 768;
        qs[b][d] = row[d];
        ks[b][d] = row[256 + d];
        vs[b][d] = row[512 + d];
    }
    __syncthreads();
    int h = tid >> 5;
    int lane = tid & 31;
    {
        int p0 = lane, p1 = lane + 32;
        int b1a = p0 >> 3, b2a = p0 & 7;
        int b1b = p1 >> 3, b2b = p1 & 7;
        const float* qa = &qs[b1a][h * 32]; const float* ka = &ks[b2a][h * 32];
        const float* qb = &qs[b1b][h * 32]; const float* kb = &ks[b2b][h * 32];
        float l0 = 0.f, l1 = 0.f;
        #pragma unroll
        for (int j = 0; j < 32; j++) { l0 += qa[j] * ka[j]; l1 += qb[j] * kb[j]; }
        const float scale = 0.17677669529663687f;
        att[h][b1a][b2a] = l0 * scale;
        att[h][b1b][b2b] = l1 * scale;
    }
    __syncwarp();
    if (lane < 8) {
        float* r = att[h][lane];
        float mx = r[0];
        #pragma unroll
        for (int j = 1; j < 8; j++) mx = fmaxf(mx, r[j]);
        float e[8]; float s = 0.f;
        #pragma unroll
        for (int j = 0; j < 8; j++) { e[j] = __expf(r[j] - mx); s += e[j]; }
        float inv = 1.f / s;
        #pragma unroll
        for (int j = 0; j < 8; j++) r[j] = e[j] * inv;
    }
    __syncwarp();
    #pragma unroll
    for (int b1 = 0; b1 < 8; b1++) {
        float acc = 0.f;
        #pragma unroll
        for (int b2 = 0; b2 < 8; b2++) acc += att[h][b1][b2] * vs[b2][h * 32 + lane];
        ctx[(size_t)(lq * 8 + b1) * 256 + h * 32 + lane] = to_tf32(acc); // feeds GEMM
    }
}

// ---------------- fused residual + LayerNorm (warp per token) ---------------
__global__ void ln_residual_kernel(const float* __restrict__ x, const float* __restrict__ y,
                                   const float* __restrict__ g, const float* __restrict__ b,
                                   float* __restrict__ out, int ntok, int rnd)
{
    int t = blockIdx.x * (blockDim.x >> 5) + (threadIdx.x >> 5);
    if (t >= ntok) return;
    int lane = threadIdx.x & 31;
    const float* xr = x + (size_t)t * 256;
    const float* yr = y + (size_t)t * 256;
    float v[8]; float s = 0.f;
    #pragma unroll
    for (int i = 0; i < 8; i++) { v[i] = xr[lane + i * 32] + yr[lane + i * 32]; s += v[i]; }
    #pragma unroll
    for (int o = 16; o > 0; o >>= 1) s += __shfl_xor_sync(~0u, s, o);
    float mean = s * (1.f / 256.f);
    float var = 0.f;
    #pragma unroll
    for (int i = 0; i < 8; i++) { float d = v[i] - mean; var += d * d; }
    #pragma unroll
    for (int o = 16; o > 0; o >>= 1) var += __shfl_xor_sync(~0u, var, o);
    float inv = rsqrtf(var * (1.f / 256.f) + 1e-5f);
    #pragma unroll
    for (int i = 0; i < 8; i++) {
        int d = lane + i * 32;
        float o2 = (v[i] - mean) * inv * g[d] + b[d];
        if (rnd) o2 = to_tf32(o2);
        out[(size_t)t * 256 + d] = o2;
    }
}

// ---------------- MS-deformable bilinear sampling (warp per (t, head)) ------
__global__ void msdeform_sample_kernel(const float* __restrict__ off,
                                       const float* __restrict__ val,
                                       float* __restrict__ out)
{
    int t = blockIdx.x;
    int lq = t >> 3, b = t & 7;
    int h = threadIdx.x >> 5;
    int lane = threadIdx.x & 31;
    int r = lq / 60, c = lq % 60;
    float refx = (c + 0.5f) * (1.f / 60.f);
    float refy = (r + 0.5f) * (1.f / 60.f);
    const float* ob = off + (size_t)t * 288;

    float wgt[12];
    {
        float mx = -1e30f;
        #pragma unroll
        for (int j = 0; j < 12; j++) { wgt[j] = ob[192 + h * 12 + j]; mx = fmaxf(mx, wgt[j]); }
        float s = 0.f;
        #pragma unroll
        for (int j = 0; j < 12; j++) { wgt[j] = __expf(wgt[j] - mx); s += wgt[j]; }
        float inv = 1.f / s;
        #pragma unroll
        for (int j = 0; j < 12; j++) wgt[j] *= inv;
    }

    const int HL[3] = {60, 30, 15};
    const int SL[3] = {0, 3600, 4500};
    float acc = 0.f;
    const float* vbase = val + (size_t)b * LIN * 256 + h * 32 + lane;
    #pragma unroll
    for (int l = 0; l < 3; l++) {
        int Wl = HL[l], Hl = HL[l];
        const float* vb = vbase + (size_t)SL[l] * 256;
        #pragma unroll
        for (int p = 0; p < 4; p++) {
            float ox = ob[((h * 3 + l) * 4 + p) * 2 + 0];
            float oy = ob[((h * 3 + l) * 4 + p) * 2 + 1];
            float x = refx * (float)Wl + ox - 0.5f;
            float y = refy * (float)Hl + oy - 0.5f;
            float x0f = floorf(x), y0f = floorf(y);
            float fx = x - x0f, fy = y - y0f;
            int x0 = (int)x0f, y0 = (int)y0f;
            float aw = wgt[l * 4 + p];
            float res = 0.f;
            #pragma unroll
            for (int cy = 0; cy < 2; cy++) {
                int yi = y0 + cy;
                if (yi < 0 || yi >= Hl) continue;
                float wy = cy ? fy : (1.f - fy);
                #pragma unroll
                for (int cx = 0; cx < 2; cx++) {
                    int xi = x0 + cx;
                    if (xi < 0 || xi >= Wl) continue;
                    float wx = cx ? fx : (1.f - fx);
                    res += wy * wx * vb[(size_t)(yi * Wl + xi) * 256];
                }
            }
            acc += aw * res;
        }
    }
    out[(size_t)t * 256 + h * 32 + lane] = to_tf32(acc);   // feeds GEMM
}

// ---------------- host launch ------------------------------------------------
static void gemm_launch(const float* A, const float* W, const float* bias, float* C,
                        int M, int N, int K, int ldc, int relu, int rnd)
{
    dim3 grid((N + BN - 1) / BN, (M + BM - 1) / BM);
    gemm_tf32_kernel<<<grid, 256, STAGE_SZ * 2 * sizeof(float)>>>(
        A, W, bias, C, M, N, K, ldc, relu, rnd);
}

static void round_launch(const float* s, float* d, int n)
{
    round_copy_kernel<<<(n / 4 + 255) / 256, 256>>>(s, d, n);
}

extern "C" void kernel_launch(void* const* d_in, const int* in_sizes, int n_in,
                              void* d_out, int out_size)
{
    const float* tgt = (const float*)d_in[0];
    const float* qp  = (const float*)d_in[1];
    const float* src = (const float*)d_in[2];
    const float* ipw = (const float*)d_in[5];
    const float* ipb = (const float*)d_in[6];
    const float* opw = (const float*)d_in[7];
    const float* opb = (const float*)d_in[8];
    const float* sow = (const float*)d_in[9];
    const float* sob = (const float*)d_in[10];
    const float* aww = (const float*)d_in[11];
    const float* awb = (const float*)d_in[12];
    const float* vpw = (const float*)d_in[13];
    const float* vpb = (const float*)d_in[14];
    const float* cow = (const float*)d_in[15];
    const float* cob = (const float*)d_in[16];
    const float* ln1g = (const float*)d_in[17];
    const float* ln1b = (const float*)d_in[18];
    const float* ln2g = (const float*)d_in[19];
    const float* ln2b = (const float*)d_in[20];
    const float* ln3g = (const float*)d_in[21];
    const float* ln3b = (const float*)d_in[22];
    const float* fw1 = (const float*)d_in[23];
    const float* fb1 = (const float*)d_in[24];
    const float* fw2 = (const float*)d_in[25];
    const float* fb2 = (const float*)d_in[26];
    float* out = (float*)d_out;

    static int smem_set = 0;
    if (!smem_set) {
        cudaFuncSetAttribute(gemm_tf32_kernel,
                             cudaFuncAttributeMaxDynamicSharedMemorySize,
                             STAGE_SZ * 2 * sizeof(float));
        smem_set = 1;
    }

    float *p_qkv, *p_ctx, *p_x1, *p_x2, *p_val, *p_off, *p_ms, *p_tmp, *p_h;
    float *p_b768, *p_b288, *p_tgt_r, *p_src_r;
    float *p_ipw, *p_opw, *p_w288, *p_vpw, *p_cow, *p_fw1, *p_fw2;
    cudaGetSymbolAddress((void**)&p_qkv, g_qkv);
    cudaGetSymbolAddress((void**)&p_ctx, g_ctx);
    cudaGetSymbolAddress((void**)&p_x1,  g_x1);
    cudaGetSymbolAddress((void**)&p_x2,  g_x2);
    cudaGetSymbolAddress((void**)&p_val, g_val);
    cudaGetSymbolAddress((void**)&p_off, g_off);
    cudaGetSymbolAddress((void**)&p_ms,  g_ms);
    cudaGetSymbolAddress((void**)&p_tmp, g_tmp);
    cudaGetSymbolAddress((void**)&p_h,   g_h);
    cudaGetSymbolAddress((void**)&p_b768, g_bias768);
    cudaGetSymbolAddress((void**)&p_b288, g_bias288);
    cudaGetSymbolAddress((void**)&p_tgt_r, g_tgt_r);
    cudaGetSymbolAddress((void**)&p_src_r, g_src_r);
    cudaGetSymbolAddress((void**)&p_ipw, g_ipw);
    cudaGetSymbolAddress((void**)&p_opw, g_opw);
    cudaGetSymbolAddress((void**)&p_w288, g_w288);
    cudaGetSymbolAddress((void**)&p_vpw, g_vpw);
    cudaGetSymbolAddress((void**)&p_cow, g_cow);
    cudaGetSymbolAddress((void**)&p_fw1, g_fw1);
    cudaGetSymbolAddress((void**)&p_fw2, g_fw2);

    // 0. tf32-round inputs and weights into scratch
    round_launch(tgt, p_tgt_r, NTOK * D);
    round_launch(src, p_src_r, NVTOK * D);
    round_launch(ipw, p_ipw, 768 * 256);
    round_launch(opw, p_opw, 256 * 256);
    round_launch(sow, p_w288, 192 * 256);
    round_launch(aww, p_w288 + 192 * 256, 96 * 256);
    round_launch(vpw, p_vpw, 256 * 256);
    round_launch(cow, p_cow, 256 * 256);
    round_launch(fw1, p_fw1, 1024 * 256);
    round_launch(fw2, p_fw2, 256 * 1024);

    // 1. fold query_pos into projection biases
    bias_adjust_kernel<<<132, 256>>>(ipw, ipb, sow, sob, aww, awb, qp);

    // 2. QKV projection -> [t][768]
    gemm_launch(p_tgt_r, p_ipw, p_b768, p_qkv, NTOK, 768, 256, 768, 0, 0);

    // 3. batch-axis self-attention
    self_attn_kernel<<<LQ, 256>>>(p_qkv, p_ctx);

    // 4. out projection
    gemm_launch(p_ctx, p_opw, opb, p_tmp, NTOK, 256, 256, 256, 0, 0);

    // 5. t = LN2(tgt + tgt2)  (rounded: feeds offsets GEMM)
    ln_residual_kernel<<<NTOK / 8, 256>>>(tgt, p_tmp, ln2g, ln2b, p_x1, NTOK, 1);

    // 6. value projection of src
    gemm_launch(p_src_r, p_vpw, vpb, p_val, NVTOK, 256, 256, 256, 0, 0);

    // 7. sampling offsets + attention-weight logits in one N=288 GEMM
    gemm_launch(p_x1, p_w288, p_b288, p_off, NTOK, 288, 256, 288, 0, 0);

    // 8. deformable bilinear sampling + weighted aggregation
    msdeform_sample_kernel<<<NTOK, 256>>>(p_off, p_val, p_ms);

    // 9. cross-attn output projection
    gemm_launch(p_ms, p_cow, cob, p_tmp, NTOK, 256, 256, 256, 0, 0);

    // 10. tq = LN1(t + tgt2)  (rounded: feeds FFN GEMM)
    ln_residual_kernel<<<NTOK / 8, 256>>>(p_x1, p_tmp, ln1g, ln1b, p_x2, NTOK, 1);

    // 11. FFN up + relu (rounded: feeds FFN2 GEMM)
    gemm_launch(p_x2, p_fw1, fb1, p_h, NTOK, DFF, 256, DFF, 1, 1);

    // 12. FFN down
    gemm_launch(p_h, p_fw2, fb2, p_tmp, NTOK, 256, DFF, 256, 0, 0);

    // 13. out = LN3(tq + ff) -> d_out (full precision)
    ln_residual_kernel<<<NTOK / 8, 256>>>(p_x2, p_tmp, ln3g, ln3b, out, NTOK, 0);
}

// round 7
// speedup vs baseline: 2.4021x; 1.1010x over previous
#include <cuda_runtime.h>
#include <cstdint>

// Problem constants
#define D 256
#define NH 8
#define HD 32
#define DFF 1024
#define BB 8
#define LQ 3600
#define NTOK (LQ * BB)          // 28800 tgt tokens (token t = lq*8 + b)
#define LIN 4725
#define NVTOK (BB * LIN)        // 37800 src tokens

// ---------------- scratch (device globals; no allocation at launch) ---------
__device__ float g_qkv[NTOK * 3 * D];
__device__ float g_ctx[NTOK * D];
__device__ float g_x1[NTOK * D];
__device__ float g_x2[NTOK * D];
__device__ float g_val[NVTOK * D];
__device__ float g_off[NTOK * 288];
__device__ float g_ms[NTOK * D];
__device__ float g_tmp[NTOK * D];
__device__ float g_h[NTOK * DFF];
__device__ float g_bias768[768];
__device__ float g_bias288[288];
// tf32-rounded copies
__device__ float g_tgt_r[NTOK * D];
__device__ float g_src_r[NVTOK * D];
__device__ float g_ipw[768 * 256];
__device__ float g_opw[256 * 256];
__device__ float g_w288[288 * 256];     // [0:192) samp_off rows, [192:288) attn_w rows
__device__ float g_vpw[256 * 256];
__device__ float g_cow[256 * 256];
__device__ float g_fw1[1024 * 256];
__device__ float g_fw2[256 * 1024];

__device__ __forceinline__ float to_tf32(float x) {
    uint32_t u;
    asm("cvt.rna.tf32.f32 %0, %1;" : "=r"(u) : "f"(x));
    return __uint_as_float(u);
}

// ---------------- single fused tf32-rounding pass over all tensors ----------
// Segment sizes in float4 units.
#define SEG0 1843200u   // tgt      -> g_tgt_r
#define SEG1 2419200u   // src      -> g_src_r
#define SEG2 49152u     // ipw      -> g_ipw
#define SEG3 16384u     // opw      -> g_opw
#define SEG4 12288u     // sow      -> g_w288[0:]
#define SEG5 6144u      // aww      -> g_w288[49152:]
#define SEG6 16384u     // vpw      -> g_vpw
#define SEG7 16384u     // cow      -> g_cow
#define SEG8 65536u     // fw1      -> g_fw1
#define SEG9 65536u     // fw2      -> g_fw2
#define SEG_TOTAL (SEG0+SEG1+SEG2+SEG3+SEG4+SEG5+SEG6+SEG7+SEG8+SEG9)

__device__ __forceinline__ float4 rnd4(float4 v) {
    v.x = to_tf32(v.x); v.y = to_tf32(v.y);
    v.z = to_tf32(v.z); v.w = to_tf32(v.w);
    return v;
}

__global__ void round_all_kernel(const float4* __restrict__ tgt, const float4* __restrict__ src,
                                 const float4* __restrict__ ipw, const float4* __restrict__ opw,
                                 const float4* __restrict__ sow, const float4* __restrict__ aww,
                                 const float4* __restrict__ vpw, const float4* __restrict__ cow,
                                 const float4* __restrict__ fw1, const float4* __restrict__ fw2)
{
    unsigned i = blockIdx.x * 256u + threadIdx.x;
    if (i >= SEG_TOTAL) return;
    if (i < SEG0) { ((float4*)g_tgt_r)[i] = rnd4(tgt[i]); return; } i -= SEG0;
    if (i < SEG1) { ((float4*)g_src_r)[i] = rnd4(src[i]); return; } i -= SEG1;
    if (i < SEG2) { ((float4*)g_ipw)[i]   = rnd4(ipw[i]); return; } i -= SEG2;
    if (i < SEG3) { ((float4*)g_opw)[i]   = rnd4(opw[i]); return; } i -= SEG3;
    if (i < SEG4) { ((float4*)g_w288)[i]  = rnd4(sow[i]); return; } i -= SEG4;
    if (i < SEG5) { ((float4*)g_w288)[SEG4 + i] = rnd4(aww[i]); return; } i -= SEG5;
    if (i < SEG6) { ((float4*)g_vpw)[i]   = rnd4(vpw[i]); return; } i -= SEG6;
    if (i < SEG7) { ((float4*)g_cow)[i]   = rnd4(cow[i]); return; } i -= SEG7;
    if (i < SEG8) { ((float4*)g_fw1)[i]   = rnd4(fw1[i]); return; } i -= SEG8;
    ((float4*)g_fw2)[i] = rnd4(fw2[i]);
}

// ---------------- bias folding: b' = b + W @ query_pos ----------------------
__global__ void bias_adjust_kernel(const float* __restrict__ ipw, const float* __restrict__ ipb,
                                   const float* __restrict__ sow, const float* __restrict__ sob,
                                   const float* __restrict__ aww, const float* __restrict__ awb,
                                   const float* __restrict__ qp)
{
    int w = blockIdx.x * (blockDim.x >> 5) + (threadIdx.x >> 5);
    int lane = threadIdx.x & 31;
    if (w < 768) {
        float s = 0.f;
        if (w < 512) {  // q,k rows get query_pos folded in; v rows do not
            const float* row = ipw + (size_t)w * D;
            #pragma unroll
            for (int i = 0; i < 8; i++) s += row[lane + i * 32] * qp[lane + i * 32];
            #pragma unroll
            for (int o = 16; o > 0; o >>= 1) s += __shfl_xor_sync(~0u, s, o);
        }
        if (lane == 0) g_bias768[w] = ipb[w] + s;
    } else if (w < 768 + 288) {
        int j = w - 768;
        const float* row; float bb;
        if (j < 192) { row = sow + (size_t)j * D; bb = sob[j]; }
        else         { row = aww + (size_t)(j - 192) * D; bb = awb[j - 192]; }
        float s = 0.f;
        #pragma unroll
        for (int i = 0; i < 8; i++) s += row[lane + i * 32] * qp[lane + i * 32];
        #pragma unroll
        for (int o = 16; o > 0; o >>= 1) s += __shfl_xor_sync(~0u, s, o);
        if (lane == 0) g_bias288[j] = bb + s;
    }
}

// ---------------- tf32 tensor-core GEMM: C = A @ W^T + bias -----------------
// A: MxK row-major (tf32-rounded). W: NxK row-major (tf32-rounded).
// 128x128 block tile, BK=32, 8 warps (2x4), warp tile 64x32, mma.m16n8k8.
// 2 CTAs/SM (regs capped at 128) to hide barrier + cp.async latency.
#define BM 128
#define BN 128
#define SROW 36                           // padded smem row stride (floats)
#define STAGE_SZ (2 * BM * SROW)          // A-tile + B-tile, floats

__device__ __forceinline__ void gemm_load_tile(
    const float* __restrict__ A, const float* __restrict__ W,
    int M, int N, int K, int m0, int n0, int k0,
    float* __restrict__ stage_base, int tid)
{
    float* As = stage_base;
    float* Bs = stage_base + BM * SROW;
    #pragma unroll
    for (int i = 0; i < 4; i++) {
        int idx = tid + i * 256;
        int row = idx >> 3, ch = (idx & 7) * 4;
        int mr = m0 + row; if (mr >= M) mr = M - 1;
        const float* gsrc = A + (size_t)mr * K + k0 + ch;
        uint32_t sdst = (uint32_t)__cvta_generic_to_shared(As + row * SROW + ch);
        asm volatile("cp.async.cg.shared.global [%0], [%1], 16;\n" :: "r"(sdst), "l"(gsrc));
    }
    #pragma unroll
    for (int i = 0; i < 4; i++) {
        int idx = tid + i * 256;
        int row = idx >> 3, ch = (idx & 7) * 4;
        int nr = n0 + row; if (nr >= N) nr = N - 1;
        const float* gsrc = W + (size_t)nr * K + k0 + ch;
        uint32_t sdst = (uint32_t)__cvta_generic_to_shared(Bs + row * SROW + ch);
        asm volatile("cp.async.cg.shared.global [%0], [%1], 16;\n" :: "r"(sdst), "l"(gsrc));
    }
    asm volatile("cp.async.commit_group;\n");
}

__global__ __launch_bounds__(256, 2)
void gemm_tf32_kernel(const float* __restrict__ A, const float* __restrict__ W,
                      const float* __restrict__ bias, float* __restrict__ C,
                      int M, int N, int K, int ldc, int relu, int rnd)
{
    extern __shared__ float smem[];
    int tid = threadIdx.x;
    int wid = tid >> 5, lane = tid & 31;
    int g = lane >> 2, t = lane & 3;
    int wm = wid >> 2, wn = wid & 3;       // 2 x 4 warp grid
    int m0 = blockIdx.y * BM, n0 = blockIdx.x * BN;

    float acc[4][4][4];
    #pragma unroll
    for (int i = 0; i < 4; i++)
        #pragma unroll
        for (int j = 0; j < 4; j++)
            #pragma unroll
            for (int c = 0; c < 4; c++) acc[i][j][c] = 0.f;

    int niter = K >> 5;
    gemm_load_tile(A, W, M, N, K, m0, n0, 0, smem, tid);

    for (int it = 0; it < niter; ++it) {
        if (it + 1 < niter) {
            gemm_load_tile(A, W, M, N, K, m0, n0, (it + 1) << 5,
                           smem + ((it + 1) & 1) * STAGE_SZ, tid);
            asm volatile("cp.async.wait_group 1;\n" ::: "memory");
        } else {
            asm volatile("cp.async.wait_group 0;\n" ::: "memory");
        }
        __syncthreads();

        const float* As = smem + (it & 1) * STAGE_SZ;
        const float* Bs = As + BM * SROW;
        #pragma unroll
        for (int ks = 0; ks < 4; ks++) {
            int kc = ks * 8;
            uint32_t a[4][4], b[4][2];
            #pragma unroll
            for (int mt = 0; mt < 4; mt++) {
                int r = wm * 64 + mt * 16 + g;
                const uint32_t* p  = (const uint32_t*)(As + r * SROW + kc + t);
                const uint32_t* p2 = (const uint32_t*)(As + (r + 8) * SROW + kc + t);
                a[mt][0] = p[0];  a[mt][2] = p[4];
                a[mt][1] = p2[0]; a[mt][3] = p2[4];
            }
            #pragma unroll
            for (int nt = 0; nt < 4; nt++) {
                int r = wn * 32 + nt * 8 + g;
                const uint32_t* p = (const uint32_t*)(Bs + r * SROW + kc + t);
                b[nt][0] = p[0]; b[nt][1] = p[4];
            }
            #pragma unroll
            for (int mt = 0; mt < 4; mt++)
                #pragma unroll
                for (int nt = 0; nt < 4; nt++) {
                    asm volatile(
                        "mma.sync.aligned.m16n8k8.row.col.f32.tf32.tf32.f32 "
                        "{%0,%1,%2,%3}, {%4,%5,%6,%7}, {%8,%9}, {%0,%1,%2,%3};\n"
                        : "+f"(acc[mt][nt][0]), "+f"(acc[mt][nt][1]),
                          "+f"(acc[mt][nt][2]), "+f"(acc[mt][nt][3])
                        : "r"(a[mt][0]), "r"(a[mt][1]), "r"(a[mt][2]), "r"(a[mt][3]),
                          "r"(b[nt][0]), "r"(b[nt][1]));
                }
        }
        __syncthreads();
    }

    // epilogue
    #pragma unroll
    for (int mt = 0; mt < 4; mt++) {
        int m = m0 + wm * 64 + mt * 16 + g;
        #pragma unroll
        for (int nt = 0; nt < 4; nt++) {
            int n = n0 + wn * 32 + nt * 8 + 2 * t;
            if (n >= N) continue;                   // N is always even; pair all-or-none
            float b0 = bias[n], b1 = bias[n + 1];
            float v0 = acc[mt][nt][0] + b0, v1 = acc[mt][nt][1] + b1;
            float v2 = acc[mt][nt][2] + b0, v3 = acc[mt][nt][3] + b1;
            if (relu) {
                v0 = fmaxf(v0, 0.f); v1 = fmaxf(v1, 0.f);
                v2 = fmaxf(v2, 0.f); v3 = fmaxf(v3, 0.f);
            }
            if (rnd) {
                v0 = to_tf32(v0); v1 = to_tf32(v1);
                v2 = to_tf32(v2); v3 = to_tf32(v3);
            }
            if (m < M)     *(float2*)(C + (size_t)m * ldc + n)       = make_float2(v0, v1);
            if (m + 8 < M) *(float2*)(C + (size_t)(m + 8) * ldc + n) = make_float2(v2, v3);
        }
    }
}

// ---------------- self-attention over the 8-element batch axis per query ----
__global__ void self_attn_kernel(const float* __restrict__ qkv, float* __restrict__ ctx)
{
    int lq = blockIdx.x;
    __shared__ float qs[8][260], ks[8][260], vs[8][260];
    __shared__ float att[8][8][8];
    int tid = threadIdx.x;
    for (int idx = tid; idx < 8 * 256; idx += 256) {
        int b = idx >> 8;
        int d = idx & 255;
        const float* row = qkv + (size_t)(lq * 8 + b) * 768;
        qs[b][d] = row[d];
        ks[b][d] = row[256 + d];
        vs[b][d] = row[512 + d];
    }
    __syncthreads();
    int h = tid >> 5;
    int lane = tid & 31;
    {
        int p0 = lane, p1 = lane + 32;
        int b1a = p0 >> 3, b2a = p0 & 7;
        int b1b = p1 >> 3, b2b = p1 & 7;
        const float* qa = &qs[b1a][h * 32]; const float* ka = &ks[b2a][h * 32];
        const float* qb = &qs[b1b][h * 32]; const float* kb = &ks[b2b][h * 32];
        float l0 = 0.f, l1 = 0.f;
        #pragma unroll
        for (int j = 0; j < 32; j++) { l0 += qa[j] * ka[j]; l1 += qb[j] * kb[j]; }
        const float scale = 0.17677669529663687f;
        att[h][b1a][b2a] = l0 * scale;
        att[h][b1b][b2b] = l1 * scale;
    }
    __syncwarp();
    if (lane < 8) {
        float* r = att[h][lane];
        float mx = r[0];
        #pragma unroll
        for (int j = 1; j < 8; j++) mx = fmaxf(mx, r[j]);
        float e[8]; float s = 0.f;
        #pragma unroll
        for (int j = 0; j < 8; j++) { e[j] = __expf(r[j] - mx); s += e[j]; }
        float inv = 1.f / s;
        #pragma unroll
        for (int j = 0; j < 8; j++) r[j] = e[j] * inv;
    }
    __syncwarp();
    #pragma unroll
    for (int b1 = 0; b1 < 8; b1++) {
        float acc = 0.f;
        #pragma unroll
        for (int b2 = 0; b2 < 8; b2++) acc += att[h][b1][b2] * vs[b2][h * 32 + lane];
        ctx[(size_t)(lq * 8 + b1) * 256 + h * 32 + lane] = to_tf32(acc); // feeds GEMM
    }
}

// ---------------- fused residual + LayerNorm (warp per token) ---------------
__global__ void ln_residual_kernel(const float* __restrict__ x, const float* __restrict__ y,
                                   const float* __restrict__ g, const float* __restrict__ b,
                                   float* __restrict__ out, int ntok, int rnd)
{
    int t = blockIdx.x * (blockDim.x >> 5) + (threadIdx.x >> 5);
    if (t >= ntok) return;
    int lane = threadIdx.x & 31;
    const float* xr = x + (size_t)t * 256;
    const float* yr = y + (size_t)t * 256;
    float v[8]; float s = 0.f;
    #pragma unroll
    for (int i = 0; i < 8; i++) { v[i] = xr[lane + i * 32] + yr[lane + i * 32]; s += v[i]; }
    #pragma unroll
    for (int o = 16; o > 0; o >>= 1) s += __shfl_xor_sync(~0u, s, o);
    float mean = s * (1.f / 256.f);
    float var = 0.f;
    #pragma unroll
    for (int i = 0; i < 8; i++) { float d = v[i] - mean; var += d * d; }
    #pragma unroll
    for (int o = 16; o > 0; o >>= 1) var += __shfl_xor_sync(~0u, var, o);
    float inv = rsqrtf(var * (1.f / 256.f) + 1e-5f);
    #pragma unroll
    for (int i = 0; i < 8; i++) {
        int d = lane + i * 32;
        float o2 = (v[i] - mean) * inv * g[d] + b[d];
        if (rnd) o2 = to_tf32(o2);
        out[(size_t)t * 256 + d] = o2;
    }
}

// ---------------- MS-deformable bilinear sampling (warp per (t, head)) ------
__global__ void msdeform_sample_kernel(const float* __restrict__ off,
                                       const float* __restrict__ val,
                                       float* __restrict__ out)
{
    int t = blockIdx.x;
    int lq = t >> 3, b = t & 7;
    int h = threadIdx.x >> 5;
    int lane = threadIdx.x & 31;
    int r = lq / 60, c = lq % 60;
    float refx = (c + 0.5f) * (1.f / 60.f);
    float refy = (r + 0.5f) * (1.f / 60.f);
    const float* ob = off + (size_t)t * 288;

    float wgt[12];
    {
        float mx = -1e30f;
        #pragma unroll
        for (int j = 0; j < 12; j++) { wgt[j] = ob[192 + h * 12 + j]; mx = fmaxf(mx, wgt[j]); }
        float s = 0.f;
        #pragma unroll
        for (int j = 0; j < 12; j++) { wgt[j] = __expf(wgt[j] - mx); s += wgt[j]; }
        float inv = 1.f / s;
        #pragma unroll
        for (int j = 0; j < 12; j++) wgt[j] *= inv;
    }

    const int HL[3] = {60, 30, 15};
    const int SL[3] = {0, 3600, 4500};
    float acc = 0.f;
    const float* vbase = val + (size_t)b * LIN * 256 + h * 32 + lane;
    #pragma unroll
    for (int l = 0; l < 3; l++) {
        int Wl = HL[l], Hl = HL[l];
        const float* vb = vbase + (size_t)SL[l] * 256;
        #pragma unroll
        for (int p = 0; p < 4; p++) {
            float ox = ob[((h * 3 + l) * 4 + p) * 2 + 0];
            float oy = ob[((h * 3 + l) * 4 + p) * 2 + 1];
            float x = refx * (float)Wl + ox - 0.5f;
            float y = refy * (float)Hl + oy - 0.5f;
            float x0f = floorf(x), y0f = floorf(y);
            float fx = x - x0f, fy = y - y0f;
            int x0 = (int)x0f, y0 = (int)y0f;
            float aw = wgt[l * 4 + p];
            float res = 0.f;
            #pragma unroll
            for (int cy = 0; cy < 2; cy++) {
                int yi = y0 + cy;
                if (yi < 0 || yi >= Hl) continue;
                float wy = cy ? fy : (1.f - fy);
                #pragma unroll
                for (int cx = 0; cx < 2; cx++) {
                    int xi = x0 + cx;
                    if (xi < 0 || xi >= Wl) continue;
                    float wx = cx ? fx : (1.f - fx);
                    res += wy * wx * vb[(size_t)(yi * Wl + xi) * 256];
                }
            }
            acc += aw * res;
        }
    }
    out[(size_t)t * 256 + h * 32 + lane] = to_tf32(acc);   // feeds GEMM
}

// ---------------- host launch ------------------------------------------------
static void gemm_launch(const float* A, const float* W, const float* bias, float* C,
                        int M, int N, int K, int ldc, int relu, int rnd)
{
    dim3 grid((N + BN - 1) / BN, (M + BM - 1) / BM);
    gemm_tf32_kernel<<<grid, 256, STAGE_SZ * 2 * sizeof(float)>>>(
        A, W, bias, C, M, N, K, ldc, relu, rnd);
}

extern "C" void kernel_launch(void* const* d_in, const int* in_sizes, int n_in,
                              void* d_out, int out_size)
{
    const float* tgt = (const float*)d_in[0];
    const float* qp  = (const float*)d_in[1];
    const float* src = (const float*)d_in[2];
    const float* ipw = (const float*)d_in[5];
    const float* ipb = (const float*)d_in[6];
    const float* opw = (const float*)d_in[7];
    const float* opb = (const float*)d_in[8];
    const float* sow = (const float*)d_in[9];
    const float* sob = (const float*)d_in[10];
    const float* aww = (const float*)d_in[11];
    const float* awb = (const float*)d_in[12];
    const float* vpw = (const float*)d_in[13];
    const float* vpb = (const float*)d_in[14];
    const float* cow = (const float*)d_in[15];
    const float* cob = (const float*)d_in[16];
    const float* ln1g = (const float*)d_in[17];
    const float* ln1b = (const float*)d_in[18];
    const float* ln2g = (const float*)d_in[19];
    const float* ln2b = (const float*)d_in[20];
    const float* ln3g = (const float*)d_in[21];
    const float* ln3b = (const float*)d_in[22];
    const float* fw1 = (const float*)d_in[23];
    const float* fb1 = (const float*)d_in[24];
    const float* fw2 = (const float*)d_in[25];
    const float* fb2 = (const float*)d_in[26];
    float* out = (float*)d_out;

    static int smem_set = 0;
    if (!smem_set) {
        cudaFuncSetAttribute(gemm_tf32_kernel,
                             cudaFuncAttributeMaxDynamicSharedMemorySize,
                             STAGE_SZ * 2 * sizeof(float));
        smem_set = 1;
    }

    float *p_qkv, *p_ctx, *p_x1, *p_x2, *p_val, *p_off, *p_ms, *p_tmp, *p_h;
    float *p_b768, *p_b288, *p_tgt_r, *p_src_r;
    float *p_ipw, *p_opw, *p_w288, *p_vpw, *p_cow, *p_fw1, *p_fw2;
    cudaGetSymbolAddress((void**)&p_qkv, g_qkv);
    cudaGetSymbolAddress((void**)&p_ctx, g_ctx);
    cudaGetSymbolAddress((void**)&p_x1,  g_x1);
    cudaGetSymbolAddress((void**)&p_x2,  g_x2);
    cudaGetSymbolAddress((void**)&p_val, g_val);
    cudaGetSymbolAddress((void**)&p_off, g_off);
    cudaGetSymbolAddress((void**)&p_ms,  g_ms);
    cudaGetSymbolAddress((void**)&p_tmp, g_tmp);
    cudaGetSymbolAddress((void**)&p_h,   g_h);
    cudaGetSymbolAddress((void**)&p_b768, g_bias768);
    cudaGetSymbolAddress((void**)&p_b288, g_bias288);
    cudaGetSymbolAddress((void**)&p_tgt_r, g_tgt_r);
    cudaGetSymbolAddress((void**)&p_src_r, g_src_r);
    cudaGetSymbolAddress((void**)&p_ipw, g_ipw);
    cudaGetSymbolAddress((void**)&p_opw, g_opw);
    cudaGetSymbolAddress((void**)&p_w288, g_w288);
    cudaGetSymbolAddress((void**)&p_vpw, g_vpw);
    cudaGetSymbolAddress((void**)&p_cow, g_cow);
    cudaGetSymbolAddress((void**)&p_fw1, g_fw1);
    cudaGetSymbolAddress((void**)&p_fw2, g_fw2);

    // 0. tf32-round all inputs/weights in ONE kernel
    round_all_kernel<<<(SEG_TOTAL + 255) / 256, 256>>>(
        (const float4*)tgt, (const float4*)src, (const float4*)ipw,
        (const float4*)opw, (const float4*)sow, (const float4*)aww,
        (const float4*)vpw, (const float4*)cow, (const float4*)fw1,
        (const float4*)fw2);

    // 1. fold query_pos into projection biases
    bias_adjust_kernel<<<132, 256>>>(ipw, ipb, sow, sob, aww, awb, qp);

    // 2. QKV projection -> [t][768]
    gemm_launch(p_tgt_r, p_ipw, p_b768, p_qkv, NTOK, 768, 256, 768, 0, 0);

    // 3. batch-axis self-attention
    self_attn_kernel<<<LQ, 256>>>(p_qkv, p_ctx);

    // 4. out projection
    gemm_launch(p_ctx, p_opw, opb, p_tmp, NTOK, 256, 256, 256, 0, 0);

    // 5. t = LN2(tgt + tgt2)  (rounded: feeds offsets GEMM)
    ln_residual_kernel<<<NTOK / 8, 256>>>(tgt, p_tmp, ln2g, ln2b, p_x1, NTOK, 1);

    // 6. value projection of src
    gemm_launch(p_src_r, p_vpw, vpb, p_val, NVTOK, 256, 256, 256, 0, 0);

    // 7. sampling offsets + attention-weight logits in one N=288 GEMM
    gemm_launch(p_x1, p_w288, p_b288, p_off, NTOK, 288, 256, 288, 0, 0);

    // 8. deformable bilinear sampling + weighted aggregation
    msdeform_sample_kernel<<<NTOK, 256>>>(p_off, p_val, p_ms);

    // 9. cross-attn output projection
    gemm_launch(p_ms, p_cow, cob, p_tmp, NTOK, 256, 256, 256, 0, 0);

    // 10. tq = LN1(t + tgt2)  (rounded: feeds FFN GEMM)
    ln_residual_kernel<<<NTOK / 8, 256>>>(p_x1, p_tmp, ln1g, ln1b, p_x2, NTOK, 1);

    // 11. FFN up + relu (rounded: feeds FFN2 GEMM)
    gemm_launch(p_x2, p_fw1, fb1, p_h, NTOK, DFF, 256, DFF, 1, 1);

    // 12. FFN down
    gemm_launch(p_h, p_fw2, fb2, p_tmp, NTOK, 256, DFF, 256, 0, 0);

    // 13. out = LN3(tq + ff) -> d_out (full precision)
    ln_residual_kernel<<<NTOK / 8, 256>>>(p_x2, p_tmp, ln3g, ln3b, out, NTOK, 0);
}

// round 12
// speedup vs baseline: 2.8958x; 1.2055x over previous
#include <cuda_runtime.h>
#include <cuda.h>
#include <cstdint>

// Problem constants
#define D 256
#define NH 8
#define HD 32
#define DFF 1024
#define BB 8
#define LQ 3600
#define NTOK (LQ * BB)          // 28800 tgt tokens (token t = lq*8 + b)
#define LIN 4725
#define NVTOK (BB * LIN)        // 37800 src tokens

// ---------------- scratch (device globals; no allocation at launch) ---------
__device__ float g_qkv[NTOK * 3 * D];
__device__ float g_ctx[NTOK * D];
__device__ float g_x1[NTOK * D];
__device__ float g_x2[NTOK * D];
__device__ float g_val[NVTOK * D];
__device__ float g_off[NTOK * 288];
__device__ float g_ms[NTOK * D];
__device__ float g_tmp[NTOK * D];
__device__ float g_h[NTOK * DFF];
__device__ float g_bias768[768];
__device__ float g_bias288[288];
// tf32-rounded copies
__device__ float g_tgt_r[NTOK * D];
__device__ float g_src_r[NVTOK * D];
__device__ float g_ipw[768 * 256];
__device__ float g_opw[256 * 256];
__device__ float g_w288[288 * 256];     // [0:192) samp_off rows, [192:288) attn_w rows
__device__ float g_vpw[256 * 256];
__device__ float g_cow[256 * 256];
__device__ float g_fw1[1024 * 256];
__device__ float g_fw2[256 * 1024];

__device__ __forceinline__ float to_tf32(float x) {
    uint32_t u;
    asm("cvt.rna.tf32.f32 %0, %1;" : "=r"(u) : "f"(x));
    return __uint_as_float(u);
}

// ---------------- single fused tf32-rounding pass over all tensors ----------
#define SEG0 1843200u   // tgt      -> g_tgt_r
#define SEG1 2419200u   // src      -> g_src_r
#define SEG2 49152u     // ipw      -> g_ipw
#define SEG3 16384u     // opw      -> g_opw
#define SEG4 12288u     // sow      -> g_w288[0:]
#define SEG5 6144u      // aww      -> g_w288[49152:]
#define SEG6 16384u     // vpw      -> g_vpw
#define SEG7 16384u     // cow      -> g_cow
#define SEG8 65536u     // fw1      -> g_fw1
#define SEG9 65536u     // fw2      -> g_fw2
#define SEG_TOTAL (SEG0+SEG1+SEG2+SEG3+SEG4+SEG5+SEG6+SEG7+SEG8+SEG9)

__device__ __forceinline__ float4 rnd4(float4 v) {
    v.x = to_tf32(v.x); v.y = to_tf32(v.y);
    v.z = to_tf32(v.z); v.w = to_tf32(v.w);
    return v;
}

__global__ void round_all_kernel(const float4* __restrict__ tgt, const float4* __restrict__ src,
                                 const float4* __restrict__ ipw, const float4* __restrict__ opw,
                                 const float4* __restrict__ sow, const float4* __restrict__ aww,
                                 const float4* __restrict__ vpw, const float4* __restrict__ cow,
                                 const float4* __restrict__ fw1, const float4* __restrict__ fw2)
{
    unsigned i = blockIdx.x * 256u + threadIdx.x;
    if (i >= SEG_TOTAL) return;
    if (i < SEG0) { ((float4*)g_tgt_r)[i] = rnd4(tgt[i]); return; } i -= SEG0;
    if (i < SEG1) { ((float4*)g_src_r)[i] = rnd4(src[i]); return; } i -= SEG1;
    if (i < SEG2) { ((float4*)g_ipw)[i]   = rnd4(ipw[i]); return; } i -= SEG2;
    if (i < SEG3) { ((float4*)g_opw)[i]   = rnd4(opw[i]); return; } i -= SEG3;
    if (i < SEG4) { ((float4*)g_w288)[i]  = rnd4(sow[i]); return; } i -= SEG4;
    if (i < SEG5) { ((float4*)g_w288)[SEG4 + i] = rnd4(aww[i]); return; } i -= SEG5;
    if (i < SEG6) { ((float4*)g_vpw)[i]   = rnd4(vpw[i]); return; } i -= SEG6;
    if (i < SEG7) { ((float4*)g_cow)[i]   = rnd4(cow[i]); return; } i -= SEG7;
    if (i < SEG8) { ((float4*)g_fw1)[i]   = rnd4(fw1[i]); return; } i -= SEG8;
    ((float4*)g_fw2)[i] = rnd4(fw2[i]);
}

// ---------------- bias folding: b' = b + W @ query_pos ----------------------
__global__ void bias_adjust_kernel(const float* __restrict__ ipw, const float* __restrict__ ipb,
                                   const float* __restrict__ sow, const float* __restrict__ sob,
                                   const float* __restrict__ aww, const float* __restrict__ awb,
                                   const float* __restrict__ qp)
{
    int w = blockIdx.x * (blockDim.x >> 5) + (threadIdx.x >> 5);
    int lane = threadIdx.x & 31;
    if (w < 768) {
        float s = 0.f;
        if (w < 512) {  // q,k rows get query_pos folded in; v rows do not
            const float* row = ipw + (size_t)w * D;
            #pragma unroll
            for (int i = 0; i < 8; i++) s += row[lane + i * 32] * qp[lane + i * 32];
            #pragma unroll
            for (int o = 16; o > 0; o >>= 1) s += __shfl_xor_sync(~0u, s, o);
        }
        if (lane == 0) g_bias768[w] = ipb[w] + s;
    } else if (w < 768 + 288) {
        int j = w - 768;
        const float* row; float bb;
        if (j < 192) { row = sow + (size_t)j * D; bb = sob[j]; }
        else         { row = aww + (size_t)(j - 192) * D; bb = awb[j - 192]; }
        float s = 0.f;
        #pragma unroll
        for (int i = 0; i < 8; i++) s += row[lane + i * 32] * qp[lane + i * 32];
        #pragma unroll
        for (int o = 16; o > 0; o >>= 1) s += __shfl_xor_sync(~0u, s, o);
        if (lane == 0) g_bias288[j] = bb + s;
    }
}

// ---------------- TMA-fed tf32 tensor-core GEMM: C = A @ W^T + bias ---------
// A: MxK row-major (tf32-rounded). W: NxK row-major (tf32-rounded).
// 128x128 block tile, BK=32, 8 warps (2x4), warp tile 64x32, mma.m16n8k8.
// Tiles arrive via cp.async.bulk.tensor.2d (SW128 swizzle) + mbarrier.
#define BM 128
#define BN 128
#define TILE_BYTES 16384u                 // 128 rows x 128 B (32 floats)
#define STAGE_BYTES 32768u                // A tile + B tile
#define SMEM_DYN (2 * STAGE_BYTES + 1024) // 2 stages + alignment slack

__device__ __forceinline__ uint32_t lds32(uint32_t a) {
    uint32_t v; asm("ld.shared.b32 %0, [%1];" : "=r"(v) : "r"(a)); return v;
}

__global__ __launch_bounds__(256, 2)
void gemm_tma_kernel(const __grid_constant__ CUtensorMap a_map,
                     const __grid_constant__ CUtensorMap b_map,
                     const float* __restrict__ bias, float* __restrict__ C,
                     int M, int N, int K, int ldc, int relu, int rnd)
{
    extern __shared__ char dsmem[];
    __shared__ __align__(8) unsigned long long mbar[2];
    int tid = threadIdx.x;
    int wid = tid >> 5, lane = tid & 31;
    int g = lane >> 2, t = lane & 3;
    int wm = wid >> 2, wn = wid & 3;       // 2 x 4 warp grid
    int m0 = blockIdx.y * BM, n0 = blockIdx.x * BN;

    uint32_t raw;
    asm("{ .reg .u64 tt; cvta.to.shared.u64 tt, %1; cvt.u32.u64 %0, tt; }"
        : "=r"(raw) : "l"(dsmem));
    uint32_t base = (raw + 1023u) & ~1023u;   // SW128 needs 1024-B aligned tiles
    uint32_t mb0;
    asm("{ .reg .u64 tt; cvta.to.shared.u64 tt, %1; cvt.u32.u64 %0, tt; }"
        : "=r"(mb0) : "l"(&mbar[0]));
    uint32_t mb1 = mb0 + 8;

    if (tid == 0) {
        asm volatile("mbarrier.init.shared.b64 [%0], 1;" :: "r"(mb0));
        asm volatile("mbarrier.init.shared.b64 [%0], 1;" :: "r"(mb1));
        asm volatile("fence.proxy.async.shared::cta;" ::: "memory");
    }
    __syncthreads();

    int niter = K >> 5;
    if (tid == 0) {   // prologue: stage 0
        asm volatile("mbarrier.arrive.expect_tx.shared.b64 _, [%0], %1;"
                     :: "r"(mb0), "r"(STAGE_BYTES));
        asm volatile("cp.async.bulk.tensor.2d.shared::cta.global.tile.mbarrier::complete_tx::bytes "
                     "[%0], [%1, {%2, %3}], [%4];"
                     :: "r"(base), "l"(&a_map), "r"(0), "r"(m0), "r"(mb0) : "memory");
        asm volatile("cp.async.bulk.tensor.2d.shared::cta.global.tile.mbarrier::complete_tx::bytes "
                     "[%0], [%1, {%2, %3}], [%4];"
                     :: "r"(base + TILE_BYTES), "l"(&b_map), "r"(0), "r"(n0), "r"(mb0) : "memory");
    }

    float acc[4][4][4];
    #pragma unroll
    for (int i = 0; i < 4; i++)
        #pragma unroll
        for (int j = 0; j < 4; j++)
            #pragma unroll
            for (int c = 0; c < 4; c++) acc[i][j][c] = 0.f;

    for (int it = 0; it < niter; ++it) {
        if (tid == 0 && it + 1 < niter) {          // prefetch next stage
            uint32_t mbn = ((it + 1) & 1) ? mb1 : mb0;
            uint32_t nst = base + ((it + 1) & 1) * STAGE_BYTES;
            int k0 = (it + 1) << 5;
            asm volatile("mbarrier.arrive.expect_tx.shared.b64 _, [%0], %1;"
                         :: "r"(mbn), "r"(STAGE_BYTES));
            asm volatile("cp.async.bulk.tensor.2d.shared::cta.global.tile.mbarrier::complete_tx::bytes "
                         "[%0], [%1, {%2, %3}], [%4];"
                         :: "r"(nst), "l"(&a_map), "r"(k0), "r"(m0), "r"(mbn) : "memory");
            asm volatile("cp.async.bulk.tensor.2d.shared::cta.global.tile.mbarrier::complete_tx::bytes "
                         "[%0], [%1, {%2, %3}], [%4];"
                         :: "r"(nst + TILE_BYTES), "l"(&b_map), "r"(k0), "r"(n0), "r"(mbn) : "memory");
        }
        {   // wait for current stage (parity = fill index & 1)
            uint32_t mbc = (it & 1) ? mb1 : mb0;
            uint32_t ph = (it >> 1) & 1;
            asm volatile(
                "{\n\t.reg .pred P;\n\t"
                "WL_%=:\n\t"
                "mbarrier.try_wait.parity.acquire.cta.shared::cta.b64 P, [%0], %1;\n\t"
                "@!P bra WL_%=;\n\t}"
                :: "r"(mbc), "r"(ph) : "memory");
        }

        uint32_t As = base + (it & 1) * STAGE_BYTES;
        uint32_t Bs = As + TILE_BYTES;
        #pragma unroll
        for (int ks = 0; ks < 4; ks++) {
            // SW128: 16B-chunk index (2ks | 2ks+1) XOR (row & 7); row&7 == g here.
            uint32_t sw0 = ((((uint32_t)(ks << 1)) ^ (uint32_t)g) << 4) | ((uint32_t)t << 2);
            uint32_t sw1 = sw0 ^ 16u;
            uint32_t a[4][4], b[4][2];
            #pragma unroll
            for (int mt = 0; mt < 4; mt++) {
                uint32_t r1 = (uint32_t)(wm * 64 + mt * 16 + g);
                a[mt][0] = lds32(As + (r1 << 7) + sw0);
                a[mt][2] = lds32(As + (r1 << 7) + sw1);
                a[mt][1] = lds32(As + ((r1 + 8) << 7) + sw0);
                a[mt][3] = lds32(As + ((r1 + 8) << 7) + sw1);
            }
            #pragma unroll
            for (int nt = 0; nt < 4; nt++) {
                uint32_t rb = (uint32_t)(wn * 32 + nt * 8 + g);
                b[nt][0] = lds32(Bs + (rb << 7) + sw0);
                b[nt][1] = lds32(Bs + (rb << 7) + sw1);
            }
            #pragma unroll
            for (int mt = 0; mt < 4; mt++)
                #pragma unroll
                for (int nt = 0; nt < 4; nt++) {
                    asm volatile(
                        "mma.sync.aligned.m16n8k8.row.col.f32.tf32.tf32.f32 "
                        "{%0,%1,%2,%3}, {%4,%5,%6,%7}, {%8,%9}, {%0,%1,%2,%3};\n"
                        : "+f"(acc[mt][nt][0]), "+f"(acc[mt][nt][1]),
                          "+f"(acc[mt][nt][2]), "+f"(acc[mt][nt][3])
                        : "r"(a[mt][0]), "r"(a[mt][1]), "r"(a[mt][2]), "r"(a[mt][3]),
                          "r"(b[nt][0]), "r"(b[nt][1]));
                }
        }
        __syncthreads();   // all reads of this stage done before it is re-filled
    }

    // epilogue
    #pragma unroll
    for (int mt = 0; mt < 4; mt++) {
        int m = m0 + wm * 64 + mt * 16 + g;
        #pragma unroll
        for (int nt = 0; nt < 4; nt++) {
            int n = n0 + wn * 32 + nt * 8 + 2 * t;
            if (n >= N) continue;                   // N always even; pair all-or-none
            float b0 = bias[n], b1 = bias[n + 1];
            float v0 = acc[mt][nt][0] + b0, v1 = acc[mt][nt][1] + b1;
            float v2 = acc[mt][nt][2] + b0, v3 = acc[mt][nt][3] + b1;
            if (relu) {
                v0 = fmaxf(v0, 0.f); v1 = fmaxf(v1, 0.f);
                v2 = fmaxf(v2, 0.f); v3 = fmaxf(v3, 0.f);
            }
            if (rnd) {
                v0 = to_tf32(v0); v1 = to_tf32(v1);
                v2 = to_tf32(v2); v3 = to_tf32(v3);
            }
            if (m < M)     *(float2*)(C + (size_t)m * ldc + n)       = make_float2(v0, v1);
            if (m + 8 < M) *(float2*)(C + (size_t)(m + 8) * ldc + n) = make_float2(v2, v3);
        }
    }
}

// ---------------- self-attention over the 8-element batch axis per query ----
__global__ void self_attn_kernel(const float* __restrict__ qkv, float* __restrict__ ctx)
{
    int lq = blockIdx.x;
    __shared__ float qs[8][260], ks[8][260], vs[8][260];
    __shared__ float att[8][8][8];
    int tid = threadIdx.x;
    for (int idx = tid; idx < 8 * 256; idx += 256) {
        int b = idx >> 8;
        int d = idx & 255;
        const float* row = qkv + (size_t)(lq * 8 + b) * 768;
        qs[b][d] = row[d];
        ks[b][d] = row[256 + d];
        vs[b][d] = row[512 + d];
    }
    __syncthreads();
    int h = tid >> 5;
    int lane = tid & 31;
    {
        int p0 = lane, p1 = lane + 32;
        int b1a = p0 >> 3, b2a = p0 & 7;
        int b1b = p1 >> 3, b2b = p1 & 7;
        const float* qa = &qs[b1a][h * 32]; const float* ka = &ks[b2a][h * 32];
        const float* qb = &qs[b1b][h * 32]; const float* kb = &ks[b2b][h * 32];
        float l0 = 0.f, l1 = 0.f;
        #pragma unroll
        for (int j = 0; j < 32; j++) { l0 += qa[j] * ka[j]; l1 += qb[j] * kb[j]; }
        const float scale = 0.17677669529663687f;
        att[h][b1a][b2a] = l0 * scale;
        att[h][b1b][b2b] = l1 * scale;
    }
    __syncwarp();
    if (lane < 8) {
        float* r = att[h][lane];
        float mx = r[0];
        #pragma unroll
        for (int j = 1; j < 8; j++) mx = fmaxf(mx, r[j]);
        float e[8]; float s = 0.f;
        #pragma unroll
        for (int j = 0; j < 8; j++) { e[j] = __expf(r[j] - mx); s += e[j]; }
        float inv = 1.f / s;
        #pragma unroll
        for (int j = 0; j < 8; j++) r[j] = e[j] * inv;
    }
    __syncwarp();
    #pragma unroll
    for (int b1 = 0; b1 < 8; b1++) {
        float acc = 0.f;
        #pragma unroll
        for (int b2 = 0; b2 < 8; b2++) acc += att[h][b1][b2] * vs[b2][h * 32 + lane];
        ctx[(size_t)(lq * 8 + b1) * 256 + h * 32 + lane] = to_tf32(acc); // feeds GEMM
    }
}

// ---------------- fused residual + LayerNorm (warp per token) ---------------
__global__ void ln_residual_kernel(const float* __restrict__ x, const float* __restrict__ y,
                                   const float* __restrict__ g, const float* __restrict__ b,
                                   float* __restrict__ out, int ntok, int rnd)
{
    int t = blockIdx.x * (blockDim.x >> 5) + (threadIdx.x >> 5);
    if (t >= ntok) return;
    int lane = threadIdx.x & 31;
    const float* xr = x + (size_t)t * 256;
    const float* yr = y + (size_t)t * 256;
    float v[8]; float s = 0.f;
    #pragma unroll
    for (int i = 0; i < 8; i++) { v[i] = xr[lane + i * 32] + yr[lane + i * 32]; s += v[i]; }
    #pragma unroll
    for (int o = 16; o > 0; o >>= 1) s += __shfl_xor_sync(~0u, s, o);
    float mean = s * (1.f / 256.f);
    float var = 0.f;
    #pragma unroll
    for (int i = 0; i < 8; i++) { float d = v[i] - mean; var += d * d; }
    #pragma unroll
    for (int o = 16; o > 0; o >>= 1) var += __shfl_xor_sync(~0u, var, o);
    float inv = rsqrtf(var * (1.f / 256.f) + 1e-5f);
    #pragma unroll
    for (int i = 0; i < 8; i++) {
        int d = lane + i * 32;
        float o2 = (v[i] - mean) * inv * g[d] + b[d];
        if (rnd) o2 = to_tf32(o2);
        out[(size_t)t * 256 + d] = o2;
    }
}

// ---------------- MS-deformable bilinear sampling (warp per (t, head)) ------
__global__ void msdeform_sample_kernel(const float* __restrict__ off,
                                       const float* __restrict__ val,
                                       float* __restrict__ out)
{
    int t = blockIdx.x;
    int lq = t >> 3, b = t & 7;
    int h = threadIdx.x >> 5;
    int lane = threadIdx.x & 31;
    int r = lq / 60, c = lq % 60;
    float refx = (c + 0.5f) * (1.f / 60.f);
    float refy = (r + 0.5f) * (1.f / 60.f);
    const float* ob = off + (size_t)t * 288;

    float wgt[12];
    {
        float mx = -1e30f;
        #pragma unroll
        for (int j = 0; j < 12; j++) { wgt[j] = ob[192 + h * 12 + j]; mx = fmaxf(mx, wgt[j]); }
        float s = 0.f;
        #pragma unroll
        for (int j = 0; j < 12; j++) { wgt[j] = __expf(wgt[j] - mx); s += wgt[j]; }
        float inv = 1.f / s;
        #pragma unroll
        for (int j = 0; j < 12; j++) wgt[j] *= inv;
    }

    const int HL[3] = {60, 30, 15};
    const int SL[3] = {0, 3600, 4500};
    float acc = 0.f;
    const float* vbase = val + (size_t)b * LIN * 256 + h * 32 + lane;
    #pragma unroll
    for (int l = 0; l < 3; l++) {
        int Wl = HL[l], Hl = HL[l];
        const float* vb = vbase + (size_t)SL[l] * 256;
        #pragma unroll
        for (int p = 0; p < 4; p++) {
            float ox = ob[((h * 3 + l) * 4 + p) * 2 + 0];
            float oy = ob[((h * 3 + l) * 4 + p) * 2 + 1];
            float x = refx * (float)Wl + ox - 0.5f;
            float y = refy * (float)Hl + oy - 0.5f;
            float x0f = floorf(x), y0f = floorf(y);
            float fx = x - x0f, fy = y - y0f;
            int x0 = (int)x0f, y0 = (int)y0f;
            float aw = wgt[l * 4 + p];
            float res = 0.f;
            #pragma unroll
            for (int cy = 0; cy < 2; cy++) {
                int yi = y0 + cy;
                if (yi < 0 || yi >= Hl) continue;
                float wy = cy ? fy : (1.f - fy);
                #pragma unroll
                for (int cx = 0; cx < 2; cx++) {
                    int xi = x0 + cx;
                    if (xi < 0 || xi >= Wl) continue;
                    float wx = cx ? fx : (1.f - fx);
                    res += wy * wx * vb[(size_t)(yi * Wl + xi) * 256];
                }
            }
            acc += aw * res;
        }
    }
    out[(size_t)t * 256 + h * 32 + lane] = to_tf32(acc);   // feeds GEMM
}

// ---------------- host launch ------------------------------------------------
typedef CUresult (*EncodeFn)(CUtensorMap*, CUtensorMapDataType, cuuint32_t, void*,
                             const cuuint64_t*, const cuuint64_t*, const cuuint32_t*,
                             const cuuint32_t*, CUtensorMapInterleave, CUtensorMapSwizzle,
                             CUtensorMapL2promotion, CUtensorMapFloatOOBfill);
static EncodeFn g_encode = nullptr;

static void make_map(CUtensorMap* m, const void* ptr, int rows, int cols /*K*/)
{
    cuuint64_t dims[2]    = {(cuuint64_t)cols, (cuuint64_t)rows};
    cuuint64_t strides[1] = {(cuuint64_t)cols * 4};
    cuuint32_t box[2]     = {32u, 128u};         // 128 B x 128 rows, SW128 atom
    cuuint32_t estr[2]    = {1u, 1u};
    g_encode(m, CU_TENSOR_MAP_DATA_TYPE_FLOAT32, 2, (void*)ptr, dims, strides, box, estr,
             CU_TENSOR_MAP_INTERLEAVE_NONE, CU_TENSOR_MAP_SWIZZLE_128B,
             CU_TENSOR_MAP_L2_PROMOTION_L2_128B, CU_TENSOR_MAP_FLOAT_OOB_FILL_NONE);
}

static void gemm_launch(const float* A, const float* W, const float* bias, float* C,
                        int M, int N, int K, int ldc, int relu, int rnd)
{
    CUtensorMap am, bm;
    make_map(&am, A, M, K);
    make_map(&bm, W, N, K);
    dim3 grid((N + BN - 1) / BN, (M + BM - 1) / BM);
    gemm_tma_kernel<<<grid, 256, SMEM_DYN>>>(am, bm, bias, C, M, N, K, ldc, relu, rnd);
}

extern "C" void kernel_launch(void* const* d_in, const int* in_sizes, int n_in,
                              void* d_out, int out_size)
{
    const float* tgt = (const float*)d_in[0];
    const float* qp  = (const float*)d_in[1];
    const float* src = (const float*)d_in[2];
    const float* ipw = (const float*)d_in[5];
    const float* ipb = (const float*)d_in[6];
    const float* opw = (const float*)d_in[7];
    const float* opb = (const float*)d_in[8];
    const float* sow = (const float*)d_in[9];
    const float* sob = (const float*)d_in[10];
    const float* aww = (const float*)d_in[11];
    const float* awb = (const float*)d_in[12];
    const float* vpw = (const float*)d_in[13];
    const float* vpb = (const float*)d_in[14];
    const float* cow = (const float*)d_in[15];
    const float* cob = (const float*)d_in[16];
    const float* ln1g = (const float*)d_in[17];
    const float* ln1b = (const float*)d_in[18];
    const float* ln2g = (const float*)d_in[19];
    const float* ln2b = (const float*)d_in[20];
    const float* ln3g = (const float*)d_in[21];
    const float* ln3b = (const float*)d_in[22];
    const float* fw1 = (const float*)d_in[23];
    const float* fb1 = (const float*)d_in[24];
    const float* fw2 = (const float*)d_in[25];
    const float* fb2 = (const float*)d_in[26];
    float* out = (float*)d_out;

    static int setup_done = 0;
    if (!setup_done) {
        cudaFuncSetAttribute(gemm_tma_kernel,
                             cudaFuncAttributeMaxDynamicSharedMemorySize, SMEM_DYN);
        cudaDriverEntryPointQueryResult st;
        void* fp = nullptr;
        cudaGetDriverEntryPoint("cuTensorMapEncodeTiled", &fp, cudaEnableDefault, &st);
        g_encode = (EncodeFn)fp;
        setup_done = 1;
    }

    float *p_qkv, *p_ctx, *p_x1, *p_x2, *p_val, *p_off, *p_ms, *p_tmp, *p_h;
    float *p_b768, *p_b288, *p_tgt_r, *p_src_r;
    float *p_ipw, *p_opw, *p_w288, *p_vpw, *p_cow, *p_fw1, *p_fw2;
    cudaGetSymbolAddress((void**)&p_qkv, g_qkv);
    cudaGetSymbolAddress((void**)&p_ctx, g_ctx);
    cudaGetSymbolAddress((void**)&p_x1,  g_x1);
    cudaGetSymbolAddress((void**)&p_x2,  g_x2);
    cudaGetSymbolAddress((void**)&p_val, g_val);
    cudaGetSymbolAddress((void**)&p_off, g_off);
    cudaGetSymbolAddress((void**)&p_ms,  g_ms);
    cudaGetSymbolAddress((void**)&p_tmp, g_tmp);
    cudaGetSymbolAddress((void**)&p_h,   g_h);
    cudaGetSymbolAddress((void**)&p_b768, g_bias768);
    cudaGetSymbolAddress((void**)&p_b288, g_bias288);
    cudaGetSymbolAddress((void**)&p_tgt_r, g_tgt_r);
    cudaGetSymbolAddress((void**)&p_src_r, g_src_r);
    cudaGetSymbolAddress((void**)&p_ipw, g_ipw);
    cudaGetSymbolAddress((void**)&p_opw, g_opw);
    cudaGetSymbolAddress((void**)&p_w288, g_w288);
    cudaGetSymbolAddress((void**)&p_vpw, g_vpw);
    cudaGetSymbolAddress((void**)&p_cow, g_cow);
    cudaGetSymbolAddress((void**)&p_fw1, g_fw1);
    cudaGetSymbolAddress((void**)&p_fw2, g_fw2);

    // 0. tf32-round all inputs/weights in ONE kernel
    round_all_kernel<<<(SEG_TOTAL + 255) / 256, 256>>>(
        (const float4*)tgt, (const float4*)src, (const float4*)ipw,
        (const float4*)opw, (const float4*)sow, (const float4*)aww,
        (const float4*)vpw, (const float4*)cow, (const float4*)fw1,
        (const float4*)fw2);

    // 1. fold query_pos into projection biases
    bias_adjust_kernel<<<132, 256>>>(ipw, ipb, sow, sob, aww, awb, qp);

    // 2. QKV projection -> [t][768]
    gemm_launch(p_tgt_r, p_ipw, p_b768, p_qkv, NTOK, 768, 256, 768, 0, 0);

    // 3. batch-axis self-attention
    self_attn_kernel<<<LQ, 256>>>(p_qkv, p_ctx);

    // 4. out projection
    gemm_launch(p_ctx, p_opw, opb, p_tmp, NTOK, 256, 256, 256, 0, 0);

    // 5. t = LN2(tgt + tgt2)  (rounded: feeds offsets GEMM)
    ln_residual_kernel<<<NTOK / 8, 256>>>(tgt, p_tmp, ln2g, ln2b, p_x1, NTOK, 1);

    // 6. value projection of src
    gemm_launch(p_src_r, p_vpw, vpb, p_val, NVTOK, 256, 256, 256, 0, 0);

    // 7. sampling offsets + attention-weight logits in one N=288 GEMM
    gemm_launch(p_x1, p_w288, p_b288, p_off, NTOK, 288, 256, 288, 0, 0);

    // 8. deformable bilinear sampling + weighted aggregation
    msdeform_sample_kernel<<<NTOK, 256>>>(p_off, p_val, p_ms);

    // 9. cross-attn output projection
    gemm_launch(p_ms, p_cow, cob, p_tmp, NTOK, 256, 256, 256, 0, 0);

    // 10. tq = LN1(t + tgt2)  (rounded: feeds FFN GEMM)
    ln_residual_kernel<<<NTOK / 8, 256>>>(p_x1, p_tmp, ln1g, ln1b, p_x2, NTOK, 1);

    // 11. FFN up + relu (rounded: feeds FFN2 GEMM)
    gemm_launch(p_x2, p_fw1, fb1, p_h, NTOK, DFF, 256, DFF, 1, 1);

    // 12. FFN down
    gemm_launch(p_h, p_fw2, fb2, p_tmp, NTOK, 256, DFF, 256, 0, 0);

    // 13. out = LN3(tq + ff) -> d_out (full precision)
    ln_residual_kernel<<<NTOK / 8, 256>>>(p_x2, p_tmp, ln3g, ln3b, out, NTOK, 0);
}